// round 14
// baseline (speedup 1.0000x reference)
#include <cuda_runtime.h>
#include <cuda_bf16.h>
#include <cuda_fp16.h>
#include <math.h>
#include <stdint.h>

#define NN 50000
#define EE 800000
#define HID 128
#define LAYERS 4

// ---------------- device scratch ----------------
__device__ __align__(16) __half g_x16A[NN * HID];  // x in fp16 (ping)
__device__ __align__(16) __half g_x16B[NN * HID];  // x in fp16 (pong)
__device__ __align__(16) __half g_xlh[NN * HID];   // xl fp16 (edge gather)
__device__ __align__(16) __half g_xrh[NN * HID];   // xr fp16
__device__ __align__(16) uint4 g_Wp[LAYERS * 2 * 2048];  // packed fp16 W frags
__device__ int g_deg[NN];
__device__ int g_rowptr[NN + 1];
__device__ int g_next[NN];
__device__ __align__(16) int g_csrc[EE];
__device__ int g_part[256];

// ---------------- prep: pack W into fp16 mma fragment order + zero (launch 0) ----------------
__global__ void k_prep(const float* __restrict__ Wl,
                       const float* __restrict__ Wr,
                       float* __restrict__ out) {
    int t = blockIdx.x * blockDim.x + threadIdx.x;
    const int totW = LAYERS * 2 * 2048;  // 16384
    if (t < totW) {
        int l = t >> 12;
        int rem = t & 4095;
        int side = rem >> 11;
        int q = rem & 2047;
        int kk = q >> 8;
        int jbp = (q >> 5) & 7;
        int lane = q & 31;
        int g = lane >> 2, tg = lane & 3;
        int k = kk * 16 + tg * 2;
        const float* W = side ? Wr : Wl;
        uint4 pk;
        {
            int j = (2 * jbp) * 8 + g;
            const float* row = W + (l << 14) + j * 128;
            __half2 b0 = __floats2half2_rn(row[k], row[k + 1]);
            __half2 b1 = __floats2half2_rn(row[k + 8], row[k + 9]);
            pk.x = *(uint32_t*)&b0;
            pk.y = *(uint32_t*)&b1;
        }
        {
            int j = (2 * jbp + 1) * 8 + g;
            const float* row = W + (l << 14) + j * 128;
            __half2 b0 = __floats2half2_rn(row[k], row[k + 1]);
            __half2 b1 = __floats2half2_rn(row[k + 8], row[k + 9]);
            pk.z = *(uint32_t*)&b0;
            pk.w = *(uint32_t*)&b1;
        }
        g_Wp[t] = pk;
    }
    if (t < NN) g_deg[t] = 0;
    if (t < 256) out[t] = 0.f;
}

// ---------------- hist (launch 1) ----------------
__global__ void k_hist(const int* __restrict__ ei) {
    int e = blockIdx.x * blockDim.x + threadIdx.x;
    if (e < EE) atomicAdd(&g_deg[ei[EE + e]], 1);
}

// ---------------- embedding -> fp16 x (launch 2) ----------------
__global__ void k_embed(const float* __restrict__ feat,
                        const float* __restrict__ Wemb,
                        const float* __restrict__ bemb,
                        __half* __restrict__ xout) {
    int gid = blockIdx.x * blockDim.x + threadIdx.x;
    if (gid >= NN * HID) return;
    int n = gid >> 7, j = gid & 127;
    float a = bemb[j];
#pragma unroll
    for (int k = 0; k < 11; k++) a += feat[n * 11 + k] * Wemb[j * 11 + k];
    xout[gid] = __float2half_rn(fmaxf(a, 0.f));
}

// ---------------- fp16 mma GEMM, fp16 A (launch 3 = profiled) ----------------
#define XROW 136

__device__ __forceinline__ uint32_t smem_u32(const void* p) {
    uint32_t a;
    asm("{ .reg .u64 t; cvta.to.shared.u64 t, %1; cvt.u32.u64 %0, t; }" : "=r"(a) : "l"(p));
    return a;
}
__device__ __forceinline__ void mma16816h(float* d, uint32_t a0, uint32_t a1,
                                          uint32_t a2, uint32_t a3,
                                          uint32_t b0, uint32_t b1) {
    asm volatile(
        "mma.sync.aligned.m16n8k16.row.col.f32.f16.f16.f32 "
        "{%0,%1,%2,%3}, {%4,%5,%6,%7}, {%8,%9}, {%0,%1,%2,%3};"
        : "+f"(d[0]), "+f"(d[1]), "+f"(d[2]), "+f"(d[3])
        : "r"(a0), "r"(a1), "r"(a2), "r"(a3), "r"(b0), "r"(b1));
}
__device__ __forceinline__ void ldsm4(uint32_t* r, uint32_t addr) {
    asm volatile("ldmatrix.sync.aligned.m8n8.x4.shared.b16 {%0,%1,%2,%3}, [%4];"
                 : "=r"(r[0]), "=r"(r[1]), "=r"(r[2]), "=r"(r[3]) : "r"(addr));
}

__global__ __launch_bounds__(512, 1) void k_gemm(const __half* __restrict__ xin,
                                                 const float* __restrict__ blp,
                                                 const float* __restrict__ brp,
                                                 const uint4* __restrict__ WpL) {
    extern __shared__ __align__(16) char smem[];
    __half* sx = (__half*)smem;

    int tid = threadIdx.x;
    int n0 = blockIdx.x * 128;
    int side = blockIdx.y;
    const uint4* Wp = WpL + side * 2048;
    const float* bias = side ? brp : blp;

    // stage A tile: pure fp16 copy, 128 rows x 16 uint4-chunks = 2048
#pragma unroll
    for (int it = 0; it < 4; it++) {
        int idx = tid + it * 512;
        int row = idx >> 4, c8 = idx & 15;
        int n = n0 + row;
        uint4 v = (n < NN) ? *(const uint4*)&xin[n * HID + c8 * 8]
                           : make_uint4(0, 0, 0, 0);
        *(uint4*)&sx[row * XROW + c8 * 8] = v;
    }
    __syncthreads();

    int wid = tid >> 5, lane = tid & 31;
    int wm = wid & 3, wn = wid >> 2;
    int g = lane >> 2, tg = lane & 3;

    int r8 = lane & 7, sel = lane >> 3;
    int lrow = (sel & 1) * 8 + r8;
    int lcol = (sel >> 1) * 8;
    uint32_t sx_base = smem_u32(sx);

    float acc[2][4][4];
#pragma unroll
    for (int mt = 0; mt < 2; mt++)
#pragma unroll
        for (int nt = 0; nt < 4; nt++)
#pragma unroll
            for (int q = 0; q < 4; q++) acc[mt][nt][q] = 0.f;

#pragma unroll
    for (int kk = 0; kk < 8; kk++) {
        int k0 = kk * 16;
        uint32_t ah[2][4];
#pragma unroll
        for (int mt = 0; mt < 2; mt++) {
            uint32_t eoff = (uint32_t)((wm * 32 + mt * 16 + lrow) * XROW + k0 + lcol) * 2;
            ldsm4(ah[mt], sx_base + eoff);
        }
        uint4 bw[2];
#pragma unroll
        for (int ntp = 0; ntp < 2; ntp++)
            bw[ntp] = Wp[kk * 256 + (wn * 2 + ntp) * 32 + lane];
#pragma unroll
        for (int ntp = 0; ntp < 2; ntp++) {
#pragma unroll
            for (int mt = 0; mt < 2; mt++) {
                mma16816h(acc[mt][ntp * 2 + 0], ah[mt][0], ah[mt][1], ah[mt][2], ah[mt][3],
                          bw[ntp].x, bw[ntp].y);
                mma16816h(acc[mt][ntp * 2 + 1], ah[mt][0], ah[mt][1], ah[mt][2], ah[mt][3],
                          bw[ntp].z, bw[ntp].w);
            }
        }
    }

    // epilogue: bias + store (side 0 -> xl fp16, side 1 -> xr fp16)
    __half2* dsth = (__half2*)(side == 0 ? g_xlh : g_xrh);
#pragma unroll
    for (int mt = 0; mt < 2; mt++) {
        int rb = n0 + wm * 32 + mt * 16;
#pragma unroll
        for (int nt = 0; nt < 4; nt++) {
            int j = wn * 32 + nt * 8 + tg * 2;
            float2 bv = *(const float2*)&bias[j];
            int r0 = rb + g, r1 = rb + 8 + g;
            if (r0 < NN)
                dsth[r0 * 64 + (j >> 1)] =
                    __floats2half2_rn(acc[mt][nt][0] + bv.x, acc[mt][nt][1] + bv.y);
            if (r1 < NN)
                dsth[r1 * 64 + (j >> 1)] =
                    __floats2half2_rn(acc[mt][nt][2] + bv.x, acc[mt][nt][3] + bv.y);
        }
    }
}

// ---------------- scan A/B + scatter (launches 4-6) ----------------
__global__ void k_scanA() {
    __shared__ int sh[8];
    int b = blockIdx.x, t = threadIdx.x;
    int i = b * 256 + t;
    int v = (i < NN) ? g_deg[i] : 0;
#pragma unroll
    for (int o = 16; o; o >>= 1) v += __shfl_xor_sync(0xffffffffu, v, o);
    if ((t & 31) == 0) sh[t >> 5] = v;
    __syncthreads();
    if (t == 0) {
        int s = 0;
#pragma unroll
        for (int i2 = 0; i2 < 8; i2++) s += sh[i2];
        g_part[b] = s;
    }
}
__global__ void k_scanB(int nb) {
    __shared__ int sh[8];
    __shared__ int s_off;
    __shared__ int wsum[8];
    int b = blockIdx.x, t = threadIdx.x;
    int pv = (t < b && t < nb) ? g_part[t] : 0;
#pragma unroll
    for (int o = 16; o; o >>= 1) pv += __shfl_xor_sync(0xffffffffu, pv, o);
    if ((t & 31) == 0) sh[t >> 5] = pv;
    __syncthreads();
    if (t == 0) {
        int s = 0;
#pragma unroll
        for (int i2 = 0; i2 < 8; i2++) s += sh[i2];
        s_off = s;
        if (b == 0) g_rowptr[NN] = EE;
    }
    __syncthreads();
    int i = b * 256 + t;
    int v = (i < NN) ? g_deg[i] : 0;
    int lane = t & 31, w = t >> 5;
    int x = v;
#pragma unroll
    for (int o = 1; o < 32; o <<= 1) {
        int y = __shfl_up_sync(0xffffffffu, x, o);
        if (lane >= o) x += y;
    }
    if (lane == 31) wsum[w] = x;
    __syncthreads();
    if (t == 0) {
        int run = 0;
#pragma unroll
        for (int i2 = 0; i2 < 8; i2++) { int tmp = wsum[i2]; wsum[i2] = run; run += tmp; }
    }
    __syncthreads();
    int excl = x - v + wsum[w] + s_off;
    if (i < NN) { g_rowptr[i] = excl; g_next[i] = excl; }
}
__global__ void k_scatter(const int* __restrict__ ei) {
    int e = blockIdx.x * blockDim.x + threadIdx.x;
    if (e < EE) {
        int d = ei[EE + e];
        int pos = atomicAdd(&g_next[d], 1);
        g_csrc[pos] = ei[e];
    }
}

// ---------------- edge aggregation: warp/dst, half2 math (R13 loop), fp16 x out ----------------
__global__ void k_edge(const float* __restrict__ attL,
                       const float* __restrict__ biasL,
                       const __half* __restrict__ xprev,
                       __half* __restrict__ xoutH,
                       float* __restrict__ xoutF,
                       int add_res, int write_f32) {
    int wid = blockIdx.x * (blockDim.x >> 5) + (threadIdx.x >> 5);
    if (wid >= NN) return;
    int lane = threadIdx.x & 31;
    int h = lane >> 3;
    int col = h * 32 + (lane & 7) * 4;
    int qc = col >> 2;
    int d = wid;

    const uint2* xl2 = (const uint2*)g_xlh;
    const uint2* xr2 = (const uint2*)g_xrh;

    uint2 ur = xr2[d * 32 + qc];
    __half2 xr01 = *(__half2*)&ur.x;
    __half2 xr23 = *(__half2*)&ur.y;
    float4 a4f = *(const float4*)&attL[col];
    __half2 a01 = __floats2half2_rn(a4f.x, a4f.y);
    __half2 a23 = __floats2half2_rn(a4f.z, a4f.w);
    const __half2 c02 = __float2half2_rn(0.2f);

    float s = 0.f;
    float ax = 0.f, ay = 0.f, az = 0.f, aw = 0.f;

    int beg = g_rowptr[d], end = g_rowptr[d + 1];
    int p = beg;
    for (; p < end && (p & 3); p++) {
        int src = g_csrc[p];
        uint2 u = xl2[src * 32 + qc];
        __half2 v01 = *(__half2*)&u.x;
        __half2 v23 = *(__half2*)&u.y;
        __half2 e01 = __hadd2(v01, xr01);
        __half2 e23 = __hadd2(v23, xr23);
        __half2 l01 = __hmax2(e01, __hmul2(e01, c02));
        __half2 l23 = __hmax2(e23, __hmul2(e23, c02));
        __half2 d2 = __hfma2(a23, l23, __hmul2(a01, l01));
        float2 df = __half22float2(d2);
        float r = df.x + df.y;
        r += __shfl_xor_sync(0xffffffffu, r, 1);
        r += __shfl_xor_sync(0xffffffffu, r, 2);
        r += __shfl_xor_sync(0xffffffffu, r, 4);
        float pp = __expf(r);
        float2 f0 = __half22float2(v01);
        float2 f1 = __half22float2(v23);
        s += pp;
        ax += pp * f0.x; ay += pp * f0.y; az += pp * f1.x; aw += pp * f1.y;
    }
    for (; p + 4 <= end; p += 4) {
        int4 s4 = *(const int4*)&g_csrc[p];
        uint2 uu[4];
        uu[0] = xl2[s4.x * 32 + qc];
        uu[1] = xl2[s4.y * 32 + qc];
        uu[2] = xl2[s4.z * 32 + qc];
        uu[3] = xl2[s4.w * 32 + qc];
        float rr[4];
        float2 vf[4][2];
#pragma unroll
        for (int j = 0; j < 4; j++) {
            __half2 v01 = *(__half2*)&uu[j].x;
            __half2 v23 = *(__half2*)&uu[j].y;
            __half2 e01 = __hadd2(v01, xr01);
            __half2 e23 = __hadd2(v23, xr23);
            __half2 l01 = __hmax2(e01, __hmul2(e01, c02));
            __half2 l23 = __hmax2(e23, __hmul2(e23, c02));
            __half2 d2 = __hfma2(a23, l23, __hmul2(a01, l01));
            float2 df = __half22float2(d2);
            rr[j] = df.x + df.y;
            vf[j][0] = __half22float2(v01);
            vf[j][1] = __half22float2(v23);
        }
#pragma unroll
        for (int j = 0; j < 4; j++) rr[j] += __shfl_xor_sync(0xffffffffu, rr[j], 1);
#pragma unroll
        for (int j = 0; j < 4; j++) rr[j] += __shfl_xor_sync(0xffffffffu, rr[j], 2);
#pragma unroll
        for (int j = 0; j < 4; j++) rr[j] += __shfl_xor_sync(0xffffffffu, rr[j], 4);
        float p0 = __expf(rr[0]);
        float p1 = __expf(rr[1]);
        float p2 = __expf(rr[2]);
        float p3 = __expf(rr[3]);
        s += p0 + p1 + p2 + p3;
        ax += p0 * vf[0][0].x + p1 * vf[1][0].x + p2 * vf[2][0].x + p3 * vf[3][0].x;
        ay += p0 * vf[0][0].y + p1 * vf[1][0].y + p2 * vf[2][0].y + p3 * vf[3][0].y;
        az += p0 * vf[0][1].x + p1 * vf[1][1].x + p2 * vf[2][1].x + p3 * vf[3][1].x;
        aw += p0 * vf[0][1].y + p1 * vf[1][1].y + p2 * vf[2][1].y + p3 * vf[3][1].y;
    }
    for (; p < end; p++) {
        int src = g_csrc[p];
        uint2 u = xl2[src * 32 + qc];
        __half2 v01 = *(__half2*)&u.x;
        __half2 v23 = *(__half2*)&u.y;
        __half2 e01 = __hadd2(v01, xr01);
        __half2 e23 = __hadd2(v23, xr23);
        __half2 l01 = __hmax2(e01, __hmul2(e01, c02));
        __half2 l23 = __hmax2(e23, __hmul2(e23, c02));
        __half2 d2 = __hfma2(a23, l23, __hmul2(a01, l01));
        float2 df = __half22float2(d2);
        float r = df.x + df.y;
        r += __shfl_xor_sync(0xffffffffu, r, 1);
        r += __shfl_xor_sync(0xffffffffu, r, 2);
        r += __shfl_xor_sync(0xffffffffu, r, 4);
        float pp = __expf(r);
        float2 f0 = __half22float2(v01);
        float2 f1 = __half22float2(v23);
        s += pp;
        ax += pp * f0.x; ay += pp * f0.y; az += pp * f1.x; aw += pp * f1.y;
    }

    float inv = (s > 0.f) ? (1.f / s) : 0.f;
    float4 b4 = *(const float4*)&biasL[col];
    float o0 = fmaxf(ax * inv + b4.x, 0.f);
    float o1 = fmaxf(ay * inv + b4.y, 0.f);
    float o2 = fmaxf(az * inv + b4.z, 0.f);
    float o3 = fmaxf(aw * inv + b4.w, 0.f);
    if (add_res) {
        uint2 up = *(const uint2*)&xprev[d * HID + col];
        float2 r0 = __half22float2(*(__half2*)&up.x);
        float2 r1 = __half22float2(*(__half2*)&up.y);
        o0 += r0.x; o1 += r0.y; o2 += r1.x; o3 += r1.y;
    }
    if (write_f32) {
        *(float4*)&xoutF[d * HID + col] = make_float4(o0, o1, o2, o3);
    } else {
        __half2 h0 = __floats2half2_rn(o0, o1);
        __half2 h1 = __floats2half2_rn(o2, o3);
        *(uint2*)&xoutH[d * HID + col] = make_uint2(*(uint32_t*)&h0, *(uint32_t*)&h1);
    }
}

// ---------------- graph pooling ----------------
__global__ void k_reduce(const float* __restrict__ x, float* __restrict__ out) {
    int col = threadIdx.x & 127;
    int rg = threadIdx.x >> 7;
    float s = 0.f, mx = 0.f;
    for (int row = blockIdx.x * 2 + rg; row < NN; row += gridDim.x * 2) {
        float v = x[row * HID + col];
        s += v;
        mx = fmaxf(mx, v);
    }
    atomicAdd(&out[col], s);
    atomicMax((int*)&out[HID + col], __float_as_int(mx));
}
__global__ void k_scale(float* out) {
    int i = threadIdx.x;
    if (i < HID) out[i] *= (1.0f / (float)NN);
}

// ---------------- launch ----------------
extern "C" void kernel_launch(void* const* d_in, const int* in_sizes, int n_in,
                              void* d_out, int out_size) {
    const float* feat = (const float*)d_in[0];
    const int* ei = (const int*)d_in[1];
    int base = 2;
    if (n_in >= 11 || (n_in > 2 && in_sizes[2] == 1)) base = 3;
    const float* Wemb = (const float*)d_in[base + 0];
    const float* bemb = (const float*)d_in[base + 1];
    const float* Wl = (const float*)d_in[base + 2];
    const float* bl = (const float*)d_in[base + 3];
    const float* Wr = (const float*)d_in[base + 4];
    const float* br = (const float*)d_in[base + 5];
    const float* att = (const float*)d_in[base + 6];
    const float* bias = (const float*)d_in[base + 7];
    float* out = (float*)d_out;

    __half *xA, *xB;
    uint4* wp;
    cudaGetSymbolAddress((void**)&xA, g_x16A);
    cudaGetSymbolAddress((void**)&xB, g_x16B);
    cudaGetSymbolAddress((void**)&wp, g_Wp);

    const int SMEM_GEMM = 128 * XROW * 2;  // 34816 B
    cudaFuncSetAttribute(k_gemm, cudaFuncAttributeMaxDynamicSharedMemorySize, SMEM_GEMM);

    float* xfinal = out + 256;

    k_prep<<<(NN + 255) / 256, 256>>>(Wl, Wr, out);
    k_hist<<<(EE + 255) / 256, 256>>>(ei);
    k_embed<<<(NN * HID + 255) / 256, 256>>>(feat, Wemb, bemb, xA);

    const int MT = (NN + 127) / 128;  // 391
    const int NB = (NN + 255) / 256;  // 196
    dim3 ggrid(MT, 2);

    // launch 3: GEMM layer 0 (profiled)
    k_gemm<<<ggrid, 512, SMEM_GEMM>>>(xA, bl, br, wp);

    k_scanA<<<NB, 256>>>();
    k_scanB<<<NB, 256>>>(NB);
    k_scatter<<<(EE + 255) / 256, 256>>>(ei);

    k_edge<<<(NN + 7) / 8, 256>>>(att, bias, xA, xB, xfinal, 0, 0);

    k_gemm<<<ggrid, 512, SMEM_GEMM>>>(xB, bl + HID, br + HID, wp + 4096);
    k_edge<<<(NN + 7) / 8, 256>>>(att + HID, bias + HID, xB, xA, xfinal, 1, 0);
    k_gemm<<<ggrid, 512, SMEM_GEMM>>>(xA, bl + 2 * HID, br + 2 * HID, wp + 8192);
    k_edge<<<(NN + 7) / 8, 256>>>(att + 2 * HID, bias + 2 * HID, xA, xB, xfinal, 1, 0);
    k_gemm<<<ggrid, 512, SMEM_GEMM>>>(xB, bl + 3 * HID, br + 3 * HID, wp + 12288);
    k_edge<<<(NN + 7) / 8, 256>>>(att + 3 * HID, bias + 3 * HID, xB, xA, xfinal, 1, 1);

    k_reduce<<<512, 256>>>(xfinal, out);
    k_scale<<<1, 128>>>(out);
}

// round 15
// speedup vs baseline: 1.4668x; 1.4668x over previous
#include <cuda_runtime.h>
#include <cuda_bf16.h>
#include <cuda_fp16.h>
#include <math.h>
#include <stdint.h>

#define NN 50000
#define EE 800000
#define HID 128
#define LAYERS 4

// ---------------- device scratch ----------------
__device__ __align__(16) float g_xA[NN * HID];
__device__ __align__(16) float g_xB[NN * HID];
__device__ __align__(16) __half g_xlh[NN * HID];   // xl fp16 (edge gather)
__device__ __align__(16) __half g_xrh[NN * HID];   // xr fp16
__device__ __align__(16) uint4 g_Wp[LAYERS * 2 * 2048];  // packed fp16 W frags
__device__ int g_deg[NN];
__device__ int g_rowptr[NN + 1];
__device__ int g_next[NN];
__device__ __align__(16) int g_csrc[EE];
__device__ int g_part[256];

// ---------------- prep: pack W into fp16 mma fragment order + zero (launch 0) ----------------
__global__ void k_prep(const float* __restrict__ Wl,
                       const float* __restrict__ Wr,
                       float* __restrict__ out) {
    int t = blockIdx.x * blockDim.x + threadIdx.x;
    const int totW = LAYERS * 2 * 2048;  // 16384
    if (t < totW) {
        int l = t >> 12;
        int rem = t & 4095;
        int side = rem >> 11;
        int q = rem & 2047;
        int kk = q >> 8;
        int jbp = (q >> 5) & 7;
        int lane = q & 31;
        int g = lane >> 2, tg = lane & 3;
        int k = kk * 16 + tg * 2;
        const float* W = side ? Wr : Wl;
        uint4 pk;
        {
            int j = (2 * jbp) * 8 + g;
            const float* row = W + (l << 14) + j * 128;
            __half2 b0 = __floats2half2_rn(row[k], row[k + 1]);
            __half2 b1 = __floats2half2_rn(row[k + 8], row[k + 9]);
            pk.x = *(uint32_t*)&b0;
            pk.y = *(uint32_t*)&b1;
        }
        {
            int j = (2 * jbp + 1) * 8 + g;
            const float* row = W + (l << 14) + j * 128;
            __half2 b0 = __floats2half2_rn(row[k], row[k + 1]);
            __half2 b1 = __floats2half2_rn(row[k + 8], row[k + 9]);
            pk.z = *(uint32_t*)&b0;
            pk.w = *(uint32_t*)&b1;
        }
        g_Wp[t] = pk;
    }
    if (t < NN) g_deg[t] = 0;
    if (t < 256) out[t] = 0.f;
}

// ---------------- hist (launch 1) ----------------
__global__ void k_hist(const int* __restrict__ ei) {
    int e = blockIdx.x * blockDim.x + threadIdx.x;
    if (e < EE) atomicAdd(&g_deg[ei[EE + e]], 1);
}

// ---------------- embedding (launch 2) ----------------
__global__ void k_embed(const float* __restrict__ feat,
                        const float* __restrict__ Wemb,
                        const float* __restrict__ bemb,
                        float* __restrict__ xout) {
    int gid = blockIdx.x * blockDim.x + threadIdx.x;
    if (gid >= NN * HID) return;
    int n = gid >> 7, j = gid & 127;
    float a = bemb[j];
#pragma unroll
    for (int k = 0; k < 11; k++) a += feat[n * 11 + k] * Wemb[j * 11 + k];
    xout[gid] = fmaxf(a, 0.f);
}

// ---------------- fp16 mma GEMM (launch 3 = profiled; byte-identical to R13) ----------------
#define XROW 136

__device__ __forceinline__ uint32_t smem_u32(const void* p) {
    uint32_t a;
    asm("{ .reg .u64 t; cvta.to.shared.u64 t, %1; cvt.u32.u64 %0, t; }" : "=r"(a) : "l"(p));
    return a;
}
__device__ __forceinline__ void mma16816h(float* d, uint32_t a0, uint32_t a1,
                                          uint32_t a2, uint32_t a3,
                                          uint32_t b0, uint32_t b1) {
    asm volatile(
        "mma.sync.aligned.m16n8k16.row.col.f32.f16.f16.f32 "
        "{%0,%1,%2,%3}, {%4,%5,%6,%7}, {%8,%9}, {%0,%1,%2,%3};"
        : "+f"(d[0]), "+f"(d[1]), "+f"(d[2]), "+f"(d[3])
        : "r"(a0), "r"(a1), "r"(a2), "r"(a3), "r"(b0), "r"(b1));
}
__device__ __forceinline__ void ldsm4(uint32_t* r, uint32_t addr) {
    asm volatile("ldmatrix.sync.aligned.m8n8.x4.shared.b16 {%0,%1,%2,%3}, [%4];"
                 : "=r"(r[0]), "=r"(r[1]), "=r"(r[2]), "=r"(r[3]) : "r"(addr));
}
__device__ __forceinline__ uint2 ldg_cg8(const uint2* p) {
    uint2 v;
    asm volatile("ld.global.cg.v2.u32 {%0,%1}, [%2];" : "=r"(v.x), "=r"(v.y) : "l"(p));
    return v;
}

__global__ __launch_bounds__(512, 1) void k_gemm(const float* __restrict__ xin,
                                                 const float* __restrict__ blp,
                                                 const float* __restrict__ brp,
                                                 const uint4* __restrict__ WpL) {
    extern __shared__ __align__(16) char smem[];
    __half* sx = (__half*)smem;

    int tid = threadIdx.x;
    int n0 = blockIdx.x * 128;
    int side = blockIdx.y;
    const uint4* Wp = WpL + side * 2048;
    const float* bias = side ? brp : blp;

#pragma unroll
    for (int it = 0; it < 8; it++) {
        int idx = tid + it * 512;
        int row = idx >> 5, g4 = idx & 31;
        int n = n0 + row;
        float4 v = (n < NN) ? *(const float4*)&xin[n * HID + g4 * 4]
                            : make_float4(0.f, 0.f, 0.f, 0.f);
        __half2 h0 = __floats2half2_rn(v.x, v.y);
        __half2 h1 = __floats2half2_rn(v.z, v.w);
        *(uint2*)&sx[row * XROW + g4 * 4] = make_uint2(*(uint32_t*)&h0, *(uint32_t*)&h1);
    }
    __syncthreads();

    int wid = tid >> 5, lane = tid & 31;
    int wm = wid & 3, wn = wid >> 2;
    int g = lane >> 2, tg = lane & 3;

    int r8 = lane & 7, sel = lane >> 3;
    int lrow = (sel & 1) * 8 + r8;
    int lcol = (sel >> 1) * 8;
    uint32_t sx_base = smem_u32(sx);

    float acc[2][4][4];
#pragma unroll
    for (int mt = 0; mt < 2; mt++)
#pragma unroll
        for (int nt = 0; nt < 4; nt++)
#pragma unroll
            for (int q = 0; q < 4; q++) acc[mt][nt][q] = 0.f;

#pragma unroll
    for (int kk = 0; kk < 8; kk++) {
        int k0 = kk * 16;
        uint32_t ah[2][4];
#pragma unroll
        for (int mt = 0; mt < 2; mt++) {
            uint32_t eoff = (uint32_t)((wm * 32 + mt * 16 + lrow) * XROW + k0 + lcol) * 2;
            ldsm4(ah[mt], sx_base + eoff);
        }
        uint4 bw[2];
#pragma unroll
        for (int ntp = 0; ntp < 2; ntp++)
            bw[ntp] = Wp[kk * 256 + (wn * 2 + ntp) * 32 + lane];
#pragma unroll
        for (int ntp = 0; ntp < 2; ntp++) {
#pragma unroll
            for (int mt = 0; mt < 2; mt++) {
                mma16816h(acc[mt][ntp * 2 + 0], ah[mt][0], ah[mt][1], ah[mt][2], ah[mt][3],
                          bw[ntp].x, bw[ntp].y);
                mma16816h(acc[mt][ntp * 2 + 1], ah[mt][0], ah[mt][1], ah[mt][2], ah[mt][3],
                          bw[ntp].z, bw[ntp].w);
            }
        }
    }

    // epilogue: bias + store (side 0 -> xl fp16, side 1 -> xr fp16)
    __half2* dsth = (__half2*)(side == 0 ? g_xlh : g_xrh);
#pragma unroll
    for (int mt = 0; mt < 2; mt++) {
        int rb = n0 + wm * 32 + mt * 16;
#pragma unroll
        for (int nt = 0; nt < 4; nt++) {
            int j = wn * 32 + nt * 8 + tg * 2;
            float2 bv = *(const float2*)&bias[j];
            int r0 = rb + g, r1 = rb + 8 + g;
            if (r0 < NN)
                dsth[r0 * 64 + (j >> 1)] =
                    __floats2half2_rn(acc[mt][nt][0] + bv.x, acc[mt][nt][1] + bv.y);
            if (r1 < NN)
                dsth[r1 * 64 + (j >> 1)] =
                    __floats2half2_rn(acc[mt][nt][2] + bv.x, acc[mt][nt][3] + bv.y);
        }
    }
}

// ---------------- scan A/B + scatter (launches 4-6) ----------------
__global__ void k_scanA() {
    __shared__ int sh[8];
    int b = blockIdx.x, t = threadIdx.x;
    int i = b * 256 + t;
    int v = (i < NN) ? g_deg[i] : 0;
#pragma unroll
    for (int o = 16; o; o >>= 1) v += __shfl_xor_sync(0xffffffffu, v, o);
    if ((t & 31) == 0) sh[t >> 5] = v;
    __syncthreads();
    if (t == 0) {
        int s = 0;
#pragma unroll
        for (int i2 = 0; i2 < 8; i2++) s += sh[i2];
        g_part[b] = s;
    }
}
__global__ void k_scanB(int nb) {
    __shared__ int sh[8];
    __shared__ int s_off;
    __shared__ int wsum[8];
    int b = blockIdx.x, t = threadIdx.x;
    int pv = (t < b && t < nb) ? g_part[t] : 0;
#pragma unroll
    for (int o = 16; o; o >>= 1) pv += __shfl_xor_sync(0xffffffffu, pv, o);
    if ((t & 31) == 0) sh[t >> 5] = pv;
    __syncthreads();
    if (t == 0) {
        int s = 0;
#pragma unroll
        for (int i2 = 0; i2 < 8; i2++) s += sh[i2];
        s_off = s;
        if (b == 0) g_rowptr[NN] = EE;
    }
    __syncthreads();
    int i = b * 256 + t;
    int v = (i < NN) ? g_deg[i] : 0;
    int lane = t & 31, w = t >> 5;
    int x = v;
#pragma unroll
    for (int o = 1; o < 32; o <<= 1) {
        int y = __shfl_up_sync(0xffffffffu, x, o);
        if (lane >= o) x += y;
    }
    if (lane == 31) wsum[w] = x;
    __syncthreads();
    if (t == 0) {
        int run = 0;
#pragma unroll
        for (int i2 = 0; i2 < 8; i2++) { int tmp = wsum[i2]; wsum[i2] = run; run += tmp; }
    }
    __syncthreads();
    int excl = x - v + wsum[w] + s_off;
    if (i < NN) { g_rowptr[i] = excl; g_next[i] = excl; }
}
__global__ void k_scatter(const int* __restrict__ ei) {
    int e = blockIdx.x * blockDim.x + threadIdx.x;
    if (e < EE) {
        int d = ei[EE + e];
        int pos = atomicAdd(&g_next[d], 1);
        g_csrc[pos] = ei[e];
    }
}

// ---------------- edge aggregation: warp/dst, half2 math, .cg gathers ----------------
__global__ void k_edge(const float* __restrict__ attL,
                       const float* __restrict__ biasL,
                       const float* __restrict__ xprev,
                       float* __restrict__ xout,
                       int add_res) {
    int wid = blockIdx.x * (blockDim.x >> 5) + (threadIdx.x >> 5);
    if (wid >= NN) return;
    int lane = threadIdx.x & 31;
    int h = lane >> 3;
    int col = h * 32 + (lane & 7) * 4;
    int qc = col >> 2;
    int d = wid;

    const uint2* xl2 = (const uint2*)g_xlh;
    const uint2* xr2 = (const uint2*)g_xrh;

    uint2 ur = xr2[d * 32 + qc];
    __half2 xr01 = *(__half2*)&ur.x;
    __half2 xr23 = *(__half2*)&ur.y;
    float4 a4f = *(const float4*)&attL[col];
    __half2 a01 = __floats2half2_rn(a4f.x, a4f.y);
    __half2 a23 = __floats2half2_rn(a4f.z, a4f.w);
    const __half2 c02 = __float2half2_rn(0.2f);

    float s = 0.f;
    float ax = 0.f, ay = 0.f, az = 0.f, aw = 0.f;

    int beg = g_rowptr[d], end = g_rowptr[d + 1];
    int p = beg;
    for (; p < end && (p & 3); p++) {
        int src = g_csrc[p];
        uint2 u = ldg_cg8(&xl2[src * 32 + qc]);
        __half2 v01 = *(__half2*)&u.x;
        __half2 v23 = *(__half2*)&u.y;
        __half2 e01 = __hadd2(v01, xr01);
        __half2 e23 = __hadd2(v23, xr23);
        __half2 l01 = __hmax2(e01, __hmul2(e01, c02));
        __half2 l23 = __hmax2(e23, __hmul2(e23, c02));
        __half2 d2 = __hfma2(a23, l23, __hmul2(a01, l01));
        float2 df = __half22float2(d2);
        float r = df.x + df.y;
        r += __shfl_xor_sync(0xffffffffu, r, 1);
        r += __shfl_xor_sync(0xffffffffu, r, 2);
        r += __shfl_xor_sync(0xffffffffu, r, 4);
        float pp = __expf(r);
        float2 f0 = __half22float2(v01);
        float2 f1 = __half22float2(v23);
        s += pp;
        ax += pp * f0.x; ay += pp * f0.y; az += pp * f1.x; aw += pp * f1.y;
    }
    for (; p + 4 <= end; p += 4) {
        int4 s4 = *(const int4*)&g_csrc[p];
        uint2 uu[4];
        uu[0] = ldg_cg8(&xl2[s4.x * 32 + qc]);
        uu[1] = ldg_cg8(&xl2[s4.y * 32 + qc]);
        uu[2] = ldg_cg8(&xl2[s4.z * 32 + qc]);
        uu[3] = ldg_cg8(&xl2[s4.w * 32 + qc]);
        float rr[4];
        float2 vf[4][2];
#pragma unroll
        for (int j = 0; j < 4; j++) {
            __half2 v01 = *(__half2*)&uu[j].x;
            __half2 v23 = *(__half2*)&uu[j].y;
            __half2 e01 = __hadd2(v01, xr01);
            __half2 e23 = __hadd2(v23, xr23);
            __half2 l01 = __hmax2(e01, __hmul2(e01, c02));
            __half2 l23 = __hmax2(e23, __hmul2(e23, c02));
            __half2 d2 = __hfma2(a23, l23, __hmul2(a01, l01));
            float2 df = __half22float2(d2);
            rr[j] = df.x + df.y;
            vf[j][0] = __half22float2(v01);
            vf[j][1] = __half22float2(v23);
        }
#pragma unroll
        for (int j = 0; j < 4; j++) rr[j] += __shfl_xor_sync(0xffffffffu, rr[j], 1);
#pragma unroll
        for (int j = 0; j < 4; j++) rr[j] += __shfl_xor_sync(0xffffffffu, rr[j], 2);
#pragma unroll
        for (int j = 0; j < 4; j++) rr[j] += __shfl_xor_sync(0xffffffffu, rr[j], 4);
        float p0 = __expf(rr[0]);
        float p1 = __expf(rr[1]);
        float p2 = __expf(rr[2]);
        float p3 = __expf(rr[3]);
        s += p0 + p1 + p2 + p3;
        ax += p0 * vf[0][0].x + p1 * vf[1][0].x + p2 * vf[2][0].x + p3 * vf[3][0].x;
        ay += p0 * vf[0][0].y + p1 * vf[1][0].y + p2 * vf[2][0].y + p3 * vf[3][0].y;
        az += p0 * vf[0][1].x + p1 * vf[1][1].x + p2 * vf[2][1].x + p3 * vf[3][1].x;
        aw += p0 * vf[0][1].y + p1 * vf[1][1].y + p2 * vf[2][1].y + p3 * vf[3][1].y;
    }
    for (; p < end; p++) {
        int src = g_csrc[p];
        uint2 u = ldg_cg8(&xl2[src * 32 + qc]);
        __half2 v01 = *(__half2*)&u.x;
        __half2 v23 = *(__half2*)&u.y;
        __half2 e01 = __hadd2(v01, xr01);
        __half2 e23 = __hadd2(v23, xr23);
        __half2 l01 = __hmax2(e01, __hmul2(e01, c02));
        __half2 l23 = __hmax2(e23, __hmul2(e23, c02));
        __half2 d2 = __hfma2(a23, l23, __hmul2(a01, l01));
        float2 df = __half22float2(d2);
        float r = df.x + df.y;
        r += __shfl_xor_sync(0xffffffffu, r, 1);
        r += __shfl_xor_sync(0xffffffffu, r, 2);
        r += __shfl_xor_sync(0xffffffffu, r, 4);
        float pp = __expf(r);
        float2 f0 = __half22float2(v01);
        float2 f1 = __half22float2(v23);
        s += pp;
        ax += pp * f0.x; ay += pp * f0.y; az += pp * f1.x; aw += pp * f1.y;
    }

    float inv = (s > 0.f) ? (1.f / s) : 0.f;
    float4 b4 = *(const float4*)&biasL[col];
    float o0 = fmaxf(ax * inv + b4.x, 0.f);
    float o1 = fmaxf(ay * inv + b4.y, 0.f);
    float o2 = fmaxf(az * inv + b4.z, 0.f);
    float o3 = fmaxf(aw * inv + b4.w, 0.f);
    if (add_res) {
        float4 rp = *(const float4*)&xprev[d * HID + col];
        o0 += rp.x; o1 += rp.y; o2 += rp.z; o3 += rp.w;
    }
    *(float4*)&xout[d * HID + col] = make_float4(o0, o1, o2, o3);
}

// ---------------- graph pooling (scale folded in) ----------------
__global__ void k_reduce(const float* __restrict__ x, float* __restrict__ out) {
    int col = threadIdx.x & 127;
    int rg = threadIdx.x >> 7;
    float s = 0.f, mx = 0.f;
    for (int row = blockIdx.x * 2 + rg; row < NN; row += gridDim.x * 2) {
        float v = x[row * HID + col];
        s += v;
        mx = fmaxf(mx, v);
    }
    atomicAdd(&out[col], s * (1.0f / (float)NN));
    atomicMax((int*)&out[HID + col], __float_as_int(mx));
}

// ---------------- launch ----------------
extern "C" void kernel_launch(void* const* d_in, const int* in_sizes, int n_in,
                              void* d_out, int out_size) {
    const float* feat = (const float*)d_in[0];
    const int* ei = (const int*)d_in[1];
    int base = 2;
    if (n_in >= 11 || (n_in > 2 && in_sizes[2] == 1)) base = 3;
    const float* Wemb = (const float*)d_in[base + 0];
    const float* bemb = (const float*)d_in[base + 1];
    const float* Wl = (const float*)d_in[base + 2];
    const float* bl = (const float*)d_in[base + 3];
    const float* Wr = (const float*)d_in[base + 4];
    const float* br = (const float*)d_in[base + 5];
    const float* att = (const float*)d_in[base + 6];
    const float* bias = (const float*)d_in[base + 7];
    float* out = (float*)d_out;

    float *xA, *xB;
    uint4* wp;
    cudaGetSymbolAddress((void**)&xA, g_xA);
    cudaGetSymbolAddress((void**)&xB, g_xB);
    cudaGetSymbolAddress((void**)&wp, g_Wp);

    const int SMEM_GEMM = 128 * XROW * 2;  // 34816 B
    cudaFuncSetAttribute(k_gemm, cudaFuncAttributeMaxDynamicSharedMemorySize, SMEM_GEMM);

    float* xfinal = out + 256;

    k_prep<<<(NN + 255) / 256, 256>>>(Wl, Wr, out);
    k_hist<<<(EE + 255) / 256, 256>>>(ei);
    k_embed<<<(NN * HID + 255) / 256, 256>>>(feat, Wemb, bemb, xA);

    const int MT = (NN + 127) / 128;  // 391
    const int NB = (NN + 255) / 256;  // 196
    dim3 ggrid(MT, 2);

    // launch 3: GEMM layer 0 (profiled — expect ~27.4us again)
    k_gemm<<<ggrid, 512, SMEM_GEMM>>>(xA, bl, br, wp);

    k_scanA<<<NB, 256>>>();
    k_scanB<<<NB, 256>>>(NB);
    k_scatter<<<(EE + 255) / 256, 256>>>(ei);

    k_edge<<<(NN + 7) / 8, 256>>>(att, bias, xA, xB, 0);

    k_gemm<<<ggrid, 512, SMEM_GEMM>>>(xB, bl + HID, br + HID, wp + 4096);
    k_edge<<<(NN + 7) / 8, 256>>>(att + HID, bias + HID, xB, xA, 1);
    k_gemm<<<ggrid, 512, SMEM_GEMM>>>(xA, bl + 2 * HID, br + 2 * HID, wp + 8192);
    k_edge<<<(NN + 7) / 8, 256>>>(att + 2 * HID, bias + 2 * HID, xA, xB, 1);
    k_gemm<<<ggrid, 512, SMEM_GEMM>>>(xB, bl + 3 * HID, br + 3 * HID, wp + 12288);
    k_edge<<<(NN + 7) / 8, 256>>>(att + 3 * HID, bias + 3 * HID, xB, xfinal, 1);

    k_reduce<<<512, 256>>>(xfinal, out);
}

// round 16
// speedup vs baseline: 1.5398x; 1.0497x over previous
#include <cuda_runtime.h>
#include <cuda_bf16.h>
#include <cuda_fp16.h>
#include <math.h>
#include <stdint.h>

#define NN 50000
#define EE 800000
#define HID 128
#define LAYERS 4

// ---------------- device scratch ----------------
__device__ __align__(16) float g_xA[NN * HID];
__device__ __align__(16) float g_xB[NN * HID];
__device__ __align__(16) __half g_xlh[NN * HID];   // xl fp16 (edge gather)
__device__ __align__(16) __half g_xrh[NN * HID];   // xr fp16
__device__ __align__(16) uint4 g_Wp[LAYERS * 2 * 2048];  // packed fp16 W frags
__device__ int g_deg[NN];
__device__ int g_rowptr[NN + 1];
__device__ int g_next[NN];
__device__ __align__(16) int g_csrc[EE];
__device__ int g_part[256];

// ---------------- prep: pack W into fp16 mma fragment order + zero (launch 0) ----------------
__global__ void k_prep(const float* __restrict__ Wl,
                       const float* __restrict__ Wr,
                       float* __restrict__ out) {
    int t = blockIdx.x * blockDim.x + threadIdx.x;
    const int totW = LAYERS * 2 * 2048;  // 16384
    if (t < totW) {
        int l = t >> 12;
        int rem = t & 4095;
        int side = rem >> 11;
        int q = rem & 2047;
        int kk = q >> 8;
        int jbp = (q >> 5) & 7;
        int lane = q & 31;
        int g = lane >> 2, tg = lane & 3;
        int k = kk * 16 + tg * 2;
        const float* W = side ? Wr : Wl;
        uint4 pk;
        {
            int j = (2 * jbp) * 8 + g;
            const float* row = W + (l << 14) + j * 128;
            __half2 b0 = __floats2half2_rn(row[k], row[k + 1]);
            __half2 b1 = __floats2half2_rn(row[k + 8], row[k + 9]);
            pk.x = *(uint32_t*)&b0;
            pk.y = *(uint32_t*)&b1;
        }
        {
            int j = (2 * jbp + 1) * 8 + g;
            const float* row = W + (l << 14) + j * 128;
            __half2 b0 = __floats2half2_rn(row[k], row[k + 1]);
            __half2 b1 = __floats2half2_rn(row[k + 8], row[k + 9]);
            pk.z = *(uint32_t*)&b0;
            pk.w = *(uint32_t*)&b1;
        }
        g_Wp[t] = pk;
    }
    if (t < NN) g_deg[t] = 0;
    if (t < 256) out[t] = 0.f;
}

// ---------------- hist (launch 1) ----------------
__global__ void k_hist(const int* __restrict__ ei) {
    int e = blockIdx.x * blockDim.x + threadIdx.x;
    if (e < EE) atomicAdd(&g_deg[ei[EE + e]], 1);
}

// ---------------- embedding (launch 2) ----------------
__global__ void k_embed(const float* __restrict__ feat,
                        const float* __restrict__ Wemb,
                        const float* __restrict__ bemb,
                        float* __restrict__ xout) {
    int gid = blockIdx.x * blockDim.x + threadIdx.x;
    if (gid >= NN * HID) return;
    int n = gid >> 7, j = gid & 127;
    float a = bemb[j];
#pragma unroll
    for (int k = 0; k < 11; k++) a += feat[n * 11 + k] * Wemb[j * 11 + k];
    xout[gid] = fmaxf(a, 0.f);
}

// ---------------- fp16 mma GEMM, 256-thread / 64-row CTA (launch 3 = profiled) ----------------
#define XROW 136

__device__ __forceinline__ uint32_t smem_u32(const void* p) {
    uint32_t a;
    asm("{ .reg .u64 t; cvta.to.shared.u64 t, %1; cvt.u32.u64 %0, t; }" : "=r"(a) : "l"(p));
    return a;
}
__device__ __forceinline__ void mma16816h(float* d, uint32_t a0, uint32_t a1,
                                          uint32_t a2, uint32_t a3,
                                          uint32_t b0, uint32_t b1) {
    asm volatile(
        "mma.sync.aligned.m16n8k16.row.col.f32.f16.f16.f32 "
        "{%0,%1,%2,%3}, {%4,%5,%6,%7}, {%8,%9}, {%0,%1,%2,%3};"
        : "+f"(d[0]), "+f"(d[1]), "+f"(d[2]), "+f"(d[3])
        : "r"(a0), "r"(a1), "r"(a2), "r"(a3), "r"(b0), "r"(b1));
}
__device__ __forceinline__ void ldsm4(uint32_t* r, uint32_t addr) {
    asm volatile("ldmatrix.sync.aligned.m8n8.x4.shared.b16 {%0,%1,%2,%3}, [%4];"
                 : "=r"(r[0]), "=r"(r[1]), "=r"(r[2]), "=r"(r[3]) : "r"(addr));
}
__device__ __forceinline__ uint2 ldg_cg8(const uint2* p) {
    uint2 v;
    asm volatile("ld.global.cg.v2.u32 {%0,%1}, [%2];" : "=r"(v.x), "=r"(v.y) : "l"(p));
    return v;
}

__global__ __launch_bounds__(256, 2) void k_gemm(const float* __restrict__ xin,
                                                 const float* __restrict__ blp,
                                                 const float* __restrict__ brp,
                                                 const uint4* __restrict__ WpL) {
    extern __shared__ __align__(16) char smem[];
    __half* sx = (__half*)smem;  // 64 x XROW fp16

    int tid = threadIdx.x;
    int n0 = blockIdx.x * 64;
    int side = blockIdx.y;
    const uint4* Wp = WpL + side * 2048;
    const float* bias = side ? brp : blp;

    // stage A tile: 64 rows x 32 float4-groups = 2048 (256 thr x 8 iters)
#pragma unroll
    for (int it = 0; it < 8; it++) {
        int idx = tid + it * 256;
        int row = idx >> 5, g4 = idx & 31;
        int n = n0 + row;
        float4 v = (n < NN) ? *(const float4*)&xin[n * HID + g4 * 4]
                            : make_float4(0.f, 0.f, 0.f, 0.f);
        __half2 h0 = __floats2half2_rn(v.x, v.y);
        __half2 h1 = __floats2half2_rn(v.z, v.w);
        *(uint2*)&sx[row * XROW + g4 * 4] = make_uint2(*(uint32_t*)&h0, *(uint32_t*)&h1);
    }
    __syncthreads();

    int wid = tid >> 5, lane = tid & 31;
    int wm = wid & 1, wn = wid >> 1;      // warp tile: rows wm*32, cols wn*32
    int g = lane >> 2, tg = lane & 3;

    int r8 = lane & 7, sel = lane >> 3;
    int lrow = (sel & 1) * 8 + r8;
    int lcol = (sel >> 1) * 8;
    uint32_t sx_base = smem_u32(sx);

    float acc[2][4][4];
#pragma unroll
    for (int mt = 0; mt < 2; mt++)
#pragma unroll
        for (int nt = 0; nt < 4; nt++)
#pragma unroll
            for (int q = 0; q < 4; q++) acc[mt][nt][q] = 0.f;

#pragma unroll
    for (int kk = 0; kk < 8; kk++) {
        int k0 = kk * 16;
        uint32_t ah[2][4];
#pragma unroll
        for (int mt = 0; mt < 2; mt++) {
            uint32_t eoff = (uint32_t)((wm * 32 + mt * 16 + lrow) * XROW + k0 + lcol) * 2;
            ldsm4(ah[mt], sx_base + eoff);
        }
        uint4 bw[2];
#pragma unroll
        for (int ntp = 0; ntp < 2; ntp++)
            bw[ntp] = Wp[kk * 256 + (wn * 2 + ntp) * 32 + lane];
#pragma unroll
        for (int ntp = 0; ntp < 2; ntp++) {
#pragma unroll
            for (int mt = 0; mt < 2; mt++) {
                mma16816h(acc[mt][ntp * 2 + 0], ah[mt][0], ah[mt][1], ah[mt][2], ah[mt][3],
                          bw[ntp].x, bw[ntp].y);
                mma16816h(acc[mt][ntp * 2 + 1], ah[mt][0], ah[mt][1], ah[mt][2], ah[mt][3],
                          bw[ntp].z, bw[ntp].w);
            }
        }
    }

    // epilogue: bias + store (side 0 -> xl fp16, side 1 -> xr fp16)
    __half2* dsth = (__half2*)(side == 0 ? g_xlh : g_xrh);
#pragma unroll
    for (int mt = 0; mt < 2; mt++) {
        int rb = n0 + wm * 32 + mt * 16;
#pragma unroll
        for (int nt = 0; nt < 4; nt++) {
            int j = wn * 32 + nt * 8 + tg * 2;
            float2 bv = *(const float2*)&bias[j];
            int r0 = rb + g, r1 = rb + 8 + g;
            if (r0 < NN)
                dsth[r0 * 64 + (j >> 1)] =
                    __floats2half2_rn(acc[mt][nt][0] + bv.x, acc[mt][nt][1] + bv.y);
            if (r1 < NN)
                dsth[r1 * 64 + (j >> 1)] =
                    __floats2half2_rn(acc[mt][nt][2] + bv.x, acc[mt][nt][3] + bv.y);
        }
    }
}

// ---------------- scan A/B + scatter (launches 4-6) ----------------
__global__ void k_scanA() {
    __shared__ int sh[8];
    int b = blockIdx.x, t = threadIdx.x;
    int i = b * 256 + t;
    int v = (i < NN) ? g_deg[i] : 0;
#pragma unroll
    for (int o = 16; o; o >>= 1) v += __shfl_xor_sync(0xffffffffu, v, o);
    if ((t & 31) == 0) sh[t >> 5] = v;
    __syncthreads();
    if (t == 0) {
        int s = 0;
#pragma unroll
        for (int i2 = 0; i2 < 8; i2++) s += sh[i2];
        g_part[b] = s;
    }
}
__global__ void k_scanB(int nb) {
    __shared__ int sh[8];
    __shared__ int s_off;
    __shared__ int wsum[8];
    int b = blockIdx.x, t = threadIdx.x;
    int pv = (t < b && t < nb) ? g_part[t] : 0;
#pragma unroll
    for (int o = 16; o; o >>= 1) pv += __shfl_xor_sync(0xffffffffu, pv, o);
    if ((t & 31) == 0) sh[t >> 5] = pv;
    __syncthreads();
    if (t == 0) {
        int s = 0;
#pragma unroll
        for (int i2 = 0; i2 < 8; i2++) s += sh[i2];
        s_off = s;
        if (b == 0) g_rowptr[NN] = EE;
    }
    __syncthreads();
    int i = b * 256 + t;
    int v = (i < NN) ? g_deg[i] : 0;
    int lane = t & 31, w = t >> 5;
    int x = v;
#pragma unroll
    for (int o = 1; o < 32; o <<= 1) {
        int y = __shfl_up_sync(0xffffffffu, x, o);
        if (lane >= o) x += y;
    }
    if (lane == 31) wsum[w] = x;
    __syncthreads();
    if (t == 0) {
        int run = 0;
#pragma unroll
        for (int i2 = 0; i2 < 8; i2++) { int tmp = wsum[i2]; wsum[i2] = run; run += tmp; }
    }
    __syncthreads();
    int excl = x - v + wsum[w] + s_off;
    if (i < NN) { g_rowptr[i] = excl; g_next[i] = excl; }
}
__global__ void k_scatter(const int* __restrict__ ei) {
    int e = blockIdx.x * blockDim.x + threadIdx.x;
    if (e < EE) {
        int d = ei[EE + e];
        int pos = atomicAdd(&g_next[d], 1);
        g_csrc[pos] = ei[e];
    }
}

// ---------------- edge aggregation: warp/dst, half2 math, .cg gathers ----------------
__global__ void k_edge(const float* __restrict__ attL,
                       const float* __restrict__ biasL,
                       const float* __restrict__ xprev,
                       float* __restrict__ xout,
                       int add_res) {
    int wid = blockIdx.x * (blockDim.x >> 5) + (threadIdx.x >> 5);
    if (wid >= NN) return;
    int lane = threadIdx.x & 31;
    int h = lane >> 3;
    int col = h * 32 + (lane & 7) * 4;
    int qc = col >> 2;
    int d = wid;

    const uint2* xl2 = (const uint2*)g_xlh;
    const uint2* xr2 = (const uint2*)g_xrh;

    uint2 ur = xr2[d * 32 + qc];
    __half2 xr01 = *(__half2*)&ur.x;
    __half2 xr23 = *(__half2*)&ur.y;
    float4 a4f = *(const float4*)&attL[col];
    __half2 a01 = __floats2half2_rn(a4f.x, a4f.y);
    __half2 a23 = __floats2half2_rn(a4f.z, a4f.w);
    const __half2 c02 = __float2half2_rn(0.2f);

    float s = 0.f;
    float ax = 0.f, ay = 0.f, az = 0.f, aw = 0.f;

    int beg = g_rowptr[d], end = g_rowptr[d + 1];
    int p = beg;
    for (; p < end && (p & 3); p++) {
        int src = g_csrc[p];
        uint2 u = ldg_cg8(&xl2[src * 32 + qc]);
        __half2 v01 = *(__half2*)&u.x;
        __half2 v23 = *(__half2*)&u.y;
        __half2 e01 = __hadd2(v01, xr01);
        __half2 e23 = __hadd2(v23, xr23);
        __half2 l01 = __hmax2(e01, __hmul2(e01, c02));
        __half2 l23 = __hmax2(e23, __hmul2(e23, c02));
        __half2 d2 = __hfma2(a23, l23, __hmul2(a01, l01));
        float2 df = __half22float2(d2);
        float r = df.x + df.y;
        r += __shfl_xor_sync(0xffffffffu, r, 1);
        r += __shfl_xor_sync(0xffffffffu, r, 2);
        r += __shfl_xor_sync(0xffffffffu, r, 4);
        float pp = __expf(r);
        float2 f0 = __half22float2(v01);
        float2 f1 = __half22float2(v23);
        s += pp;
        ax += pp * f0.x; ay += pp * f0.y; az += pp * f1.x; aw += pp * f1.y;
    }
    for (; p + 4 <= end; p += 4) {
        int4 s4 = *(const int4*)&g_csrc[p];
        uint2 uu[4];
        uu[0] = ldg_cg8(&xl2[s4.x * 32 + qc]);
        uu[1] = ldg_cg8(&xl2[s4.y * 32 + qc]);
        uu[2] = ldg_cg8(&xl2[s4.z * 32 + qc]);
        uu[3] = ldg_cg8(&xl2[s4.w * 32 + qc]);
        float rr[4];
        float2 vf[4][2];
#pragma unroll
        for (int j = 0; j < 4; j++) {
            __half2 v01 = *(__half2*)&uu[j].x;
            __half2 v23 = *(__half2*)&uu[j].y;
            __half2 e01 = __hadd2(v01, xr01);
            __half2 e23 = __hadd2(v23, xr23);
            __half2 l01 = __hmax2(e01, __hmul2(e01, c02));
            __half2 l23 = __hmax2(e23, __hmul2(e23, c02));
            __half2 d2 = __hfma2(a23, l23, __hmul2(a01, l01));
            float2 df = __half22float2(d2);
            rr[j] = df.x + df.y;
            vf[j][0] = __half22float2(v01);
            vf[j][1] = __half22float2(v23);
        }
#pragma unroll
        for (int j = 0; j < 4; j++) rr[j] += __shfl_xor_sync(0xffffffffu, rr[j], 1);
#pragma unroll
        for (int j = 0; j < 4; j++) rr[j] += __shfl_xor_sync(0xffffffffu, rr[j], 2);
#pragma unroll
        for (int j = 0; j < 4; j++) rr[j] += __shfl_xor_sync(0xffffffffu, rr[j], 4);
        float p0 = __expf(rr[0]);
        float p1 = __expf(rr[1]);
        float p2 = __expf(rr[2]);
        float p3 = __expf(rr[3]);
        s += p0 + p1 + p2 + p3;
        ax += p0 * vf[0][0].x + p1 * vf[1][0].x + p2 * vf[2][0].x + p3 * vf[3][0].x;
        ay += p0 * vf[0][0].y + p1 * vf[1][0].y + p2 * vf[2][0].y + p3 * vf[3][0].y;
        az += p0 * vf[0][1].x + p1 * vf[1][1].x + p2 * vf[2][1].x + p3 * vf[3][1].x;
        aw += p0 * vf[0][1].y + p1 * vf[1][1].y + p2 * vf[2][1].y + p3 * vf[3][1].y;
    }
    for (; p < end; p++) {
        int src = g_csrc[p];
        uint2 u = ldg_cg8(&xl2[src * 32 + qc]);
        __half2 v01 = *(__half2*)&u.x;
        __half2 v23 = *(__half2*)&u.y;
        __half2 e01 = __hadd2(v01, xr01);
        __half2 e23 = __hadd2(v23, xr23);
        __half2 l01 = __hmax2(e01, __hmul2(e01, c02));
        __half2 l23 = __hmax2(e23, __hmul2(e23, c02));
        __half2 d2 = __hfma2(a23, l23, __hmul2(a01, l01));
        float2 df = __half22float2(d2);
        float r = df.x + df.y;
        r += __shfl_xor_sync(0xffffffffu, r, 1);
        r += __shfl_xor_sync(0xffffffffu, r, 2);
        r += __shfl_xor_sync(0xffffffffu, r, 4);
        float pp = __expf(r);
        float2 f0 = __half22float2(v01);
        float2 f1 = __half22float2(v23);
        s += pp;
        ax += pp * f0.x; ay += pp * f0.y; az += pp * f1.x; aw += pp * f1.y;
    }

    float inv = (s > 0.f) ? (1.f / s) : 0.f;
    float4 b4 = *(const float4*)&biasL[col];
    float o0 = fmaxf(ax * inv + b4.x, 0.f);
    float o1 = fmaxf(ay * inv + b4.y, 0.f);
    float o2 = fmaxf(az * inv + b4.z, 0.f);
    float o3 = fmaxf(aw * inv + b4.w, 0.f);
    if (add_res) {
        float4 rp = *(const float4*)&xprev[d * HID + col];
        o0 += rp.x; o1 += rp.y; o2 += rp.z; o3 += rp.w;
    }
    *(float4*)&xout[d * HID + col] = make_float4(o0, o1, o2, o3);
}

// ---------------- graph pooling (scale folded in) ----------------
__global__ void k_reduce(const float* __restrict__ x, float* __restrict__ out) {
    int col = threadIdx.x & 127;
    int rg = threadIdx.x >> 7;
    float s = 0.f, mx = 0.f;
    for (int row = blockIdx.x * 2 + rg; row < NN; row += gridDim.x * 2) {
        float v = x[row * HID + col];
        s += v;
        mx = fmaxf(mx, v);
    }
    atomicAdd(&out[col], s * (1.0f / (float)NN));
    atomicMax((int*)&out[HID + col], __float_as_int(mx));
}

// ---------------- launch ----------------
extern "C" void kernel_launch(void* const* d_in, const int* in_sizes, int n_in,
                              void* d_out, int out_size) {
    const float* feat = (const float*)d_in[0];
    const int* ei = (const int*)d_in[1];
    int base = 2;
    if (n_in >= 11 || (n_in > 2 && in_sizes[2] == 1)) base = 3;
    const float* Wemb = (const float*)d_in[base + 0];
    const float* bemb = (const float*)d_in[base + 1];
    const float* Wl = (const float*)d_in[base + 2];
    const float* bl = (const float*)d_in[base + 3];
    const float* Wr = (const float*)d_in[base + 4];
    const float* br = (const float*)d_in[base + 5];
    const float* att = (const float*)d_in[base + 6];
    const float* bias = (const float*)d_in[base + 7];
    float* out = (float*)d_out;

    float *xA, *xB;
    uint4* wp;
    cudaGetSymbolAddress((void**)&xA, g_xA);
    cudaGetSymbolAddress((void**)&xB, g_xB);
    cudaGetSymbolAddress((void**)&wp, g_Wp);

    const int SMEM_GEMM = 64 * XROW * 2;  // 17408 B (64-row fp16 tile)
    cudaFuncSetAttribute(k_gemm, cudaFuncAttributeMaxDynamicSharedMemorySize, SMEM_GEMM);

    float* xfinal = out + 256;

    k_prep<<<(NN + 255) / 256, 256>>>(Wl, Wr, out);
    k_hist<<<(EE + 255) / 256, 256>>>(ei);
    k_embed<<<(NN * HID + 255) / 256, 256>>>(feat, Wemb, bemb, xA);

    const int MT = (NN + 63) / 64;  // 782
    const int NB = (NN + 255) / 256;  // 196
    dim3 ggrid(MT, 2);

    // launch 3: GEMM layer 0 (profiled)
    k_gemm<<<ggrid, 256, SMEM_GEMM>>>(xA, bl, br, wp);

    k_scanA<<<NB, 256>>>();
    k_scanB<<<NB, 256>>>(NB);
    k_scatter<<<(EE + 255) / 256, 256>>>(ei);

    k_edge<<<(NN + 7) / 8, 256>>>(att, bias, xA, xB, 0);

    k_gemm<<<ggrid, 256, SMEM_GEMM>>>(xB, bl + HID, br + HID, wp + 4096);
    k_edge<<<(NN + 7) / 8, 256>>>(att + HID, bias + HID, xB, xA, 1);
    k_gemm<<<ggrid, 256, SMEM_GEMM>>>(xA, bl + 2 * HID, br + 2 * HID, wp + 8192);
    k_edge<<<(NN + 7) / 8, 256>>>(att + 2 * HID, bias + 2 * HID, xA, xB, 1);
    k_gemm<<<ggrid, 256, SMEM_GEMM>>>(xB, bl + 3 * HID, br + 3 * HID, wp + 12288);
    k_edge<<<(NN + 7) / 8, 256>>>(att + 3 * HID, bias + 3 * HID, xB, xfinal, 1);

    k_reduce<<<512, 256>>>(xfinal, out);
}